// round 5
// baseline (speedup 1.0000x reference)
#include <cuda_runtime.h>
#include <cuda_bf16.h>
#include <math.h>

#define BATCH 2
#define NPTS  8192
#define CH    128
#define KNN   8
#define MTOT  (BATCH * NPTS)

// ---------------- scratch (no allocations allowed) ----------------
__device__ float g_q[MTOT * CH];
__device__ float g_k[MTOT * CH];
__device__ float g_v[MTOT * CH];
__device__ int   g_idx[MTOT * KNN];
__device__ uint4 g_agg2[MTOT * 64];    // agg split, X-pattern (hi,lo,hi,lo)

// ---------------- f32x2 helpers (Blackwell packed fp32 math) ----------------
typedef unsigned long long ull;
__device__ __forceinline__ void fma2(ull& d, ull a, ull b) {
    asm("fma.rn.f32x2 %0, %1, %2, %0;" : "+l"(d) : "l"(a), "l"(b));
}
__device__ __forceinline__ ull mul2(ull a, ull b) {
    ull r; asm("mul.rn.f32x2 %0, %1, %2;" : "=l"(r) : "l"(a), "l"(b)); return r;
}
__device__ __forceinline__ ull pk2(float x, float y) {
    ull r; asm("mov.b64 %0, {%1, %2};" : "=l"(r) : "f"(x), "f"(y)); return r;
}
__device__ __forceinline__ float2 unpk2(ull v) {
    float2 f; asm("mov.b64 {%0, %1}, %2;" : "=f"(f.x), "=f"(f.y) : "l"(v)); return f;
}

// ---------------- fp32 -> (hi,lo) bf16 split helpers ----------------
__device__ __forceinline__ void split_bf16(float x, unsigned short& h, unsigned short& l) {
    __nv_bfloat16 hb = __float2bfloat16(x);
    float hf = __bfloat162float(hb);
    __nv_bfloat16 lb = __float2bfloat16(x - hf);
    h = __bfloat16_as_ushort(hb);
    l = __bfloat16_as_ushort(lb);
}
__device__ __forceinline__ unsigned pack_hilo(float x) {   // X-pattern word (hi,lo)
    unsigned short h, l; split_bf16(x, h, l);
    return ((unsigned)l << 16) | (unsigned)h;
}
__device__ __forceinline__ void pack_w(float x, unsigned& p0, unsigned& p1) { // (hi,hi),(lo,lo)
    unsigned short h, l; split_bf16(x, h, l);
    p0 = ((unsigned)h << 16) | h;
    p1 = ((unsigned)l << 16) | l;
}

// ---------------- tensor-core GEMM:  Y = X @ W^T via bf16 split-K ----------------
// W always fp32, split inline. X either fp32 (SPLIT_X) or pre-split uint4.
// CTA = 128x128, 256 threads = 8 warps (4x2), warp tile 32x64, mma.m16n8k16.
// smem rows padded to 144B -> conflict-free LDS.32 fragment loads.
template <bool SPLIT_X>
__device__ __forceinline__ void mma_gemm_tile(const void* __restrict__ Xv,
                                              const float* __restrict__ Wf,
                                              float* __restrict__ Y, int m0,
                                              char* smem)
{
    unsigned char* xs = (unsigned char*)smem;
    unsigned char* ws = (unsigned char*)smem + 128 * 144;
    const int tid  = threadIdx.x;
    const int lane = tid & 31;
    const int warp = tid >> 5;
    const int wm   = warp >> 1;
    const int wn   = warp & 1;
    const int g    = lane >> 2;
    const int c4   = lane & 3;

    float acc[2][8][4];
#pragma unroll
    for (int i = 0; i < 2; i++)
#pragma unroll
        for (int t = 0; t < 8; t++)
#pragma unroll
            for (int r = 0; r < 4; r++) acc[i][t][r] = 0.f;

    for (int kc = 0; kc < 8; kc++) {        // K' = 512 in chunks of 64
        __syncthreads();
#pragma unroll
        for (int i = 0; i < 4; i++) {
            int s  = tid + i * 256;         // 0..1023
            int r  = s >> 3;                // row 0..127
            int f4 = s & 7;                 // 16B unit 0..7
            if (SPLIT_X) {
                const float* X = (const float*)Xv;
                float2 xv = *(const float2*)(X + (size_t)(m0 + r) * CH + kc * 16 + f4 * 2);
                unsigned p0 = pack_hilo(xv.x), p1 = pack_hilo(xv.y);
                *(uint4*)(xs + r * 144 + f4 * 16) = make_uint4(p0, p0, p1, p1);
            } else {
                const uint4* X2 = (const uint4*)Xv;
                *(uint4*)(xs + r * 144 + f4 * 16) = X2[(size_t)(m0 + r) * 64 + kc * 8 + f4];
            }
            float2 wv = *(const float2*)(Wf + (size_t)r * CH + kc * 16 + f4 * 2);
            unsigned a0, a1, b0, b1;
            pack_w(wv.x, a0, a1);
            pack_w(wv.y, b0, b1);
            *(uint4*)(ws + r * 144 + f4 * 16) = make_uint4(a0, a1, b0, b1);
        }
        __syncthreads();
#pragma unroll
        for (int ks = 0; ks < 4; ks++) {    // 4 x k16 steps
            unsigned a[2][4], b[8][2];
#pragma unroll
            for (int i = 0; i < 2; i++)
#pragma unroll
                for (int j = 0; j < 4; j++) {
                    int row = wm * 32 + i * 16 + g + 8 * (j & 1);
                    int off = ks * 32 + (j >> 1) * 16 + c4 * 4;
                    a[i][j] = *(const unsigned*)(xs + row * 144 + off);
                }
#pragma unroll
            for (int t = 0; t < 8; t++)
#pragma unroll
                for (int r = 0; r < 2; r++) {
                    int n   = wn * 64 + t * 8 + g;
                    int off = ks * 32 + r * 16 + c4 * 4;
                    b[t][r] = *(const unsigned*)(ws + n * 144 + off);
                }
#pragma unroll
            for (int i = 0; i < 2; i++)
#pragma unroll
                for (int t = 0; t < 8; t++)
                    asm volatile(
                        "mma.sync.aligned.m16n8k16.row.col.f32.bf16.bf16.f32 "
                        "{%0,%1,%2,%3}, {%4,%5,%6,%7}, {%8,%9}, {%0,%1,%2,%3};"
                        : "+f"(acc[i][t][0]), "+f"(acc[i][t][1]),
                          "+f"(acc[i][t][2]), "+f"(acc[i][t][3])
                        : "r"(a[i][0]), "r"(a[i][1]), "r"(a[i][2]), "r"(a[i][3]),
                          "r"(b[t][0]), "r"(b[t][1]));
        }
    }
#pragma unroll
    for (int i = 0; i < 2; i++)
#pragma unroll
        for (int t = 0; t < 8; t++) {
            int row = m0 + wm * 32 + i * 16 + g;
            int col = wn * 64 + t * 8 + 2 * c4;
            *(float2*)(Y + (size_t)row * CH + col)       = make_float2(acc[i][t][0], acc[i][t][1]);
            *(float2*)(Y + (size_t)(row + 8) * CH + col) = make_float2(acc[i][t][2], acc[i][t][3]);
        }
}

// ---------------- KNN body: warp-collective top-8, e = csq - 2*dot ----------------
#define QW     4
#define WARPS  8
#define CCH    2048
#define KNN_BLOCKS (NPTS / (WARPS * QW) * BATCH)   // 512

__device__ __forceinline__ void knn_body(const float* __restrict__ coords,
                                         int* __restrict__ out_idx,
                                         int bid, char* smemraw)
{
    float4* sc = (float4*)smemraw;
    const unsigned full = 0xffffffffu;
    const int b     = bid >> 8;                 // 0..1 (256 x-blocks per batch)
    const int xblk  = bid & 255;
    const int warp  = threadIdx.x >> 5;
    const int lane  = threadIdx.x & 31;
    const int qbase = xblk * (WARPS * QW) + warp * QW;
    const float* cb = coords + (size_t)b * NPTS * 3;

    ull qxp[QW], qyp[QW], qzp[QW];
#pragma unroll
    for (int u = 0; u < QW; u++) {
        float x = cb[(qbase + u) * 3 + 0];
        float y = cb[(qbase + u) * 3 + 1];
        float z = cb[(qbase + u) * 3 + 2];
        qxp[u] = pk2(x, x); qyp[u] = pk2(y, y); qzp[u] = pk2(z, z);
    }
    const ull n2p = pk2(-2.f, -2.f);

    float val[QW]; int idx[QW]; float thr[QW];
#pragma unroll
    for (int u = 0; u < QW; u++) { val[u] = 3.0e38f; idx[u] = -1; thr[u] = 3.0e38f; }

    for (int c0 = 0; c0 < NPTS; c0 += CCH) {
        __syncthreads();
        for (int t = threadIdx.x; t < CCH; t += 256) {
            float x = cb[(c0 + t) * 3 + 0];
            float y = cb[(c0 + t) * 3 + 1];
            float z = cb[(c0 + t) * 3 + 2];
            sc[t] = make_float4(x, y, z, fmaf(z, z, fmaf(y, y, x * x)));
        }
        __syncthreads();

        for (int t = lane; t < CCH; t += 128) {       // 4 candidates per lane
            float4 ca  = sc[t];
            float4 cbv = sc[t + 32];
            float4 cc  = sc[t + 64];
            float4 cd  = sc[t + 96];
            ull X01 = pk2(ca.x, cbv.x), Y01 = pk2(ca.y, cbv.y);
            ull Z01 = pk2(ca.z, cbv.z), S01 = pk2(ca.w, cbv.w);
            ull X23 = pk2(cc.x, cd.x),  Y23 = pk2(cc.y, cd.y);
            ull Z23 = pk2(cc.z, cd.z),  S23 = pk2(cc.w, cd.w);
            int tb = c0 + t - lane;                   // warp-uniform
#pragma unroll
            for (int u = 0; u < QW; u++) {
                ull d01 = mul2(qxp[u], X01);
                fma2(d01, qyp[u], Y01);
                fma2(d01, qzp[u], Z01);
                ull e01 = S01; fma2(e01, n2p, d01);   // e = csq - 2*dot
                ull d23 = mul2(qxp[u], X23);
                fma2(d23, qyp[u], Y23);
                fma2(d23, qzp[u], Z23);
                ull e23 = S23; fma2(e23, n2p, d23);
                float2 f01 = unpk2(e01);
                float2 f23 = unpk2(e23);

                // lane-min insert protocol: one ballot per round; consumed
                // values are discarded (thr only decreases -> safe).
                unsigned rm = 0xF;
                for (;;) {
                    float lm = 3.0e38f; int li = 0;
                    if ((rm & 1) && f01.x < lm) { lm = f01.x; li = 0; }
                    if ((rm & 2) && f01.y < lm) { lm = f01.y; li = 1; }
                    if ((rm & 4) && f23.x < lm) { lm = f23.x; li = 2; }
                    if ((rm & 8) && f23.y < lm) { lm = f23.y; li = 3; }
                    unsigned m0b = __ballot_sync(full, lm < thr[u]);
                    if (!m0b) break;
                    unsigned m = m0b;
                    while (m) {
                        int src = __ffs(m) - 1;
                        m &= m - 1;
                        float dn = __shfl_sync(full, lm, src);
                        if (dn < thr[u]) {            // warp-uniform
                            int sl = __shfl_sync(full, li, src);
                            int in = tb + (sl << 5) + src;
                            float pv = __shfl_up_sync(full, val[u], 1);
                            int   pi = __shfl_up_sync(full, idx[u], 1);
                            unsigned le = __ballot_sync(full, val[u] <= dn);
                            int pos = __popc(le & 0xff);
                            if (lane == pos)                 { val[u] = dn; idx[u] = in; }
                            else if (lane > pos && lane < 8) { val[u] = pv; idx[u] = pi; }
                            thr[u] = __shfl_sync(full, val[u], 7);
                        }
                    }
                    if ((m0b >> lane) & 1) rm &= ~(1u << li);   // consume examined min
                }
            }
        }
    }

    if (lane < KNN) {
#pragma unroll
        for (int u = 0; u < QW; u++)
            out_idx[((size_t)b * NPTS + qbase + u) * KNN + lane] = idx[u];
    }
}

// ---------------- fused phase-1 kernel: KNN blocks first, then qkv GEMM ----------
__global__ __launch_bounds__(256) void fused_qkv_knn(const float* __restrict__ feats,
                                                     const float* __restrict__ coords,
                                                     const float* __restrict__ Wq,
                                                     const float* __restrict__ Wk,
                                                     const float* __restrict__ Wv,
                                                     int* __restrict__ out_idx)
{
    extern __shared__ char smem[];
    if (blockIdx.x < KNN_BLOCKS) {
        knn_body(coords, out_idx, blockIdx.x, smem);
    } else {
        int gb = blockIdx.x - KNN_BLOCKS;          // 0..383
        int w  = gb >> 7;                          // 0..2
        int m0 = (gb & 127) * 128;
        const float* W = (w == 0) ? Wq : (w == 1) ? Wk : Wv;
        float* Y = (w == 0) ? g_q : (w == 1) ? g_k : g_v;
        mma_gemm_tile<true>(feats, W, Y, m0, smem);
    }
}

__global__ __launch_bounds__(256) void out_mma_kernel(const float* __restrict__ Wo,
                                                      float* __restrict__ out)
{
    extern __shared__ char smem[];
    mma_gemm_tile<false>(g_agg2, Wo, out, blockIdx.x * 128, smem);
}

// ---------------- attention over K=8 neighbors (writes bf16 hi/lo agg) ----------
__global__ __launch_bounds__(256) void attn_kernel(const float* __restrict__ coords,
                                                   const float* __restrict__ logg)
{
    const int gq   = blockIdx.x * 8 + (threadIdx.x >> 5);
    const int b    = gq >> 13;
    const int q    = gq & (NPTS - 1);
    const int lane = threadIdx.x & 31;
    const float lg = *logg;
    const float inv_sqrt_c = 0.08838834764831845f;   // 1/sqrt(128)

    const float* qrow = g_q + (size_t)gq * CH;
    float qv[4];
#pragma unroll
    for (int p = 0; p < 4; p++) qv[p] = qrow[lane + 32 * p];

    const float* cb = coords + (size_t)b * NPTS * 3;
    const float qx = cb[q * 3 + 0], qy = cb[q * 3 + 1], qz = cb[q * 3 + 2];

    int nb[KNN];
#pragma unroll
    for (int t = 0; t < KNN; t++) nb[t] = g_idx[(size_t)gq * KNN + t];

    float sc[KNN];
#pragma unroll
    for (int t = 0; t < KNN; t++) {
        const float* kr = g_k + ((size_t)b * NPTS + nb[t]) * CH;
        float d = 0.f;
#pragma unroll
        for (int p = 0; p < 4; p++) d = fmaf(qv[p], kr[lane + 32 * p], d);
#pragma unroll
        for (int off = 16; off; off >>= 1) d += __shfl_xor_sync(0xffffffffu, d, off);
        float dx = qx - cb[nb[t] * 3 + 0];
        float dy = qy - cb[nb[t] * 3 + 1];
        float dz = qz - cb[nb[t] * 3 + 2];
        float d2 = fmaf(dz, dz, fmaf(dy, dy, dx * dx));
        float dist = (d2 > 0.f) ? sqrtf(d2) : 0.f;     // _safe_norm
        float gw = expf(lg * dist);
        sc[t] = d * inv_sqrt_c * gw;
    }
    float m = sc[0];
#pragma unroll
    for (int t = 1; t < KNN; t++) m = fmaxf(m, sc[t]);
    float ssum = 0.f;
#pragma unroll
    for (int t = 0; t < KNN; t++) { sc[t] = expf(sc[t] - m); ssum += sc[t]; }
    float inv = 1.f / ssum;

    float acc[4] = {0.f, 0.f, 0.f, 0.f};
#pragma unroll
    for (int t = 0; t < KNN; t++) {
        const float* vr = g_v + ((size_t)b * NPTS + nb[t]) * CH;
        float wt = sc[t] * inv;
#pragma unroll
        for (int p = 0; p < 4; p++) acc[p] = fmaf(wt, vr[lane + 32 * p], acc[p]);
    }
    // write agg directly in bf16 hi/lo X-pattern for the output GEMM
#pragma unroll
    for (int p = 0; p < 4; p++) {
        unsigned pk = pack_hilo(acc[p]);
        ((uint2*)g_agg2)[(size_t)gq * 128 + lane + 32 * p] = make_uint2(pk, pk);
    }
}

// ---------------- launch ----------------
#define SMEM_BYTES (128 * 144 * 2)   // 36864: gemm needs 36864, knn needs 32768

extern "C" void kernel_launch(void* const* d_in, const int* in_sizes, int n_in,
                              void* d_out, int out_size)
{
    const float* feats  = (const float*)d_in[0];
    const float* coords = (const float*)d_in[1];
    const float* Wq     = (const float*)d_in[2];
    const float* Wk     = (const float*)d_in[3];
    const float* Wv     = (const float*)d_in[4];
    const float* Wo     = (const float*)d_in[5];
    const float* logg   = (const float*)d_in[6];
    float* out = (float*)d_out;

    int* idx_ptr = nullptr;
    cudaGetSymbolAddress((void**)&idx_ptr, g_idx);

    // phase 1: KNN (512 blocks, scheduled first) + qkv tensor GEMMs (384 blocks)
    fused_qkv_knn<<<KNN_BLOCKS + 3 * (MTOT / 128), 256, SMEM_BYTES>>>(
        feats, coords, Wq, Wk, Wv, idx_ptr);

    // phase 2: neighbor attention -> g_agg2 (bf16 hi/lo)
    attn_kernel<<<MTOT / 8, 256>>>(coords, logg);

    // phase 3: output projection (Wo split inline)
    out_mma_kernel<<<MTOT / 128, 256, SMEM_BYTES>>>(Wo, out);
}